// round 1
// baseline (speedup 1.0000x reference)
#include <cuda_runtime.h>
#include <math.h>

// ---------------------------------------------------------------------------
// ContrastiveEnergyLearning: fused 4-layer MLP energy + contrastive reductions
// Round 1: exact fp32 with packed fma.rn.f32x2 (FFMA2), anchor-half of layer 1
// factored out and precomputed once per batch item.
// ---------------------------------------------------------------------------

#define NB      32768
#define NNEG    16
#define RPB     17
#define RTOT    (NB * RPB)          // 557056
#define TILE_M  64
#define NBLK    (RTOT / TILE_M)     // 8704
#define TEMP_INV (1.0f / 0.07f)

// device-global scratch (allocation-free per harness rules)
__device__ float g_A[NB * 256];     // anchor @ W1[:, :256]^T + b1  (32 MB)
__device__ float g_energy[RTOT];    // per-row energies (2.2 MB)
__device__ float g_part[128][4];    // per-block reduction partials

typedef unsigned long long u64;

__device__ __forceinline__ u64 pk(float x, float y) {
    u64 r; asm("mov.b64 %0,{%1,%2};" : "=l"(r) : "f"(x), "f"(y)); return r;
}
__device__ __forceinline__ float2 upk(u64 v) {
    float2 r; asm("mov.b64 {%0,%1},%2;" : "=f"(r.x), "=f"(r.y) : "l"(v)); return r;
}
__device__ __forceinline__ void fma2(u64 &d, u64 a, u64 b) {
    asm("fma.rn.f32x2 %0,%1,%2,%0;" : "+l"(d) : "l"(a), "l"(b));
}
__device__ __forceinline__ float gelu_exact(float x) {
    return 0.5f * x * (1.0f + erff(x * 0.7071067811865476f));
}

// Load a [NO x KC] chunk of a row-major weight W[NO][ld] (columns k0..k0+KC)
// into SMEM transposed as Wst[k][o], with an XOR swizzle (o ^ ((k>>2)&7)*4)
// making both the scattered stores and the float4 reads conflict-free-ish.
template <int NO, int KC>
__device__ __forceinline__ void load_w(float* Wst, const float* __restrict__ W,
                                       int ld, int k0, int tid) {
    constexpr int NQ = KC / 4;
    constexpr int TOT = NO * NQ;
    #pragma unroll
    for (int i = tid; i < TOT; i += 256) {
        int o  = i / NQ;
        int kg = i - o * NQ;
        float4 v = *(const float4*)(W + (size_t)o * ld + k0 + (kg << 2));
        int oo = o ^ ((kg & 7) << 2);
        int kb = kg << 2;
        Wst[(kb + 0) * NO + oo] = v.x;
        Wst[(kb + 1) * NO + oo] = v.y;
        Wst[(kb + 2) * NO + oo] = v.z;
        Wst[(kb + 3) * NO + oo] = v.w;
    }
}

// 64x256 tile GEMM chunk (K slice of 32): acc[8][4 pairs] += Xs * Wst^T
__device__ __forceinline__ void gemm256_chunk(const float* Xs, const float* Wst,
                                              int kc, int m0, int o0, u64 acc[8][4]) {
    #pragma unroll
    for (int k4 = 0; k4 < 32; k4 += 4) {
        float4 xv[8];
        #pragma unroll
        for (int i = 0; i < 8; i++)
            xv[i] = *(const float4*)&Xs[(m0 + i) * 256 + kc + k4];
        const int q  = ((k4 >> 2) & 7) << 2;
        const int oo = o0 ^ q;
        #pragma unroll
        for (int c = 0; c < 4; c++) {
            const float* wr = &Wst[(k4 + c) * 256];
            float4 w0 = *(const float4*)(wr + oo);
            float4 w1 = *(const float4*)(wr + (oo ^ 4));
            u64 wa = pk(w0.x, w0.y), wb = pk(w0.z, w0.w);
            u64 wc = pk(w1.x, w1.y), wd = pk(w1.z, w1.w);
            #pragma unroll
            for (int i = 0; i < 8; i++) {
                float x = (c == 0) ? xv[i].x : (c == 1) ? xv[i].y
                        : (c == 2) ? xv[i].z : xv[i].w;
                u64 xx = pk(x, x);
                fma2(acc[i][0], xx, wa);
                fma2(acc[i][1], xx, wb);
                fma2(acc[i][2], xx, wc);
                fma2(acc[i][3], xx, wd);
            }
        }
    }
}

// ---------------------------------------------------------------------------
// Kernel 1: A = anchor @ W1[:, :256]^T + b1   (pre-activation partial)
// ---------------------------------------------------------------------------
__global__ void __launch_bounds__(256, 1)
precompA(const float* __restrict__ anchor, const float* __restrict__ W1,
         const float* __restrict__ b1) {
    extern __shared__ float sm[];
    float* Xs  = sm;             // 64*256
    float* Wst = sm + 64 * 256;  // 32*256

    const int tid = threadIdx.x;
    const int r0  = blockIdx.x * TILE_M;

    for (int i = tid; i < 64 * 64; i += 256) {
        int m = i >> 6, c = i & 63;
        ((float4*)Xs)[m * 64 + c] =
            ((const float4*)(anchor + (size_t)(r0 + m) * 256))[c];
    }

    const int m0 = (tid >> 5) * 8;
    const int o0 = (tid & 31) * 8;

    u64 acc[8][4];
    float4 bb0 = *(const float4*)(b1 + o0);
    float4 bb1 = *(const float4*)(b1 + o0 + 4);
    #pragma unroll
    for (int i = 0; i < 8; i++) {
        acc[i][0] = pk(bb0.x, bb0.y); acc[i][1] = pk(bb0.z, bb0.w);
        acc[i][2] = pk(bb1.x, bb1.y); acc[i][3] = pk(bb1.z, bb1.w);
    }

    for (int kc = 0; kc < 256; kc += 32) {
        __syncthreads();
        load_w<256, 32>(Wst, W1, 512, kc, tid);
        __syncthreads();
        gemm256_chunk(Xs, Wst, kc, m0, o0, acc);
    }

    #pragma unroll
    for (int i = 0; i < 8; i++) {
        float2 p0 = upk(acc[i][0]), p1 = upk(acc[i][1]);
        float2 p2 = upk(acc[i][2]), p3 = upk(acc[i][3]);
        float4 v0 = {p0.x, p0.y, p1.x, p1.y};
        float4 v1 = {p2.x, p2.y, p3.x, p3.y};
        size_t base = (size_t)(r0 + m0 + i) * 256 + o0;
        *(float4*)(g_A + base)     = v0;
        *(float4*)(g_A + base + 4) = v1;
    }
}

// ---------------------------------------------------------------------------
// Kernel 2: fused energy: h1=gelu(A[b] + y@W1y^T); h2=gelu(h1@W2^T+b2);
//           h3=gelu(h2@W3^T+b3); e = h3.W4 + b4
// ---------------------------------------------------------------------------
__global__ void __launch_bounds__(256, 1)
energyK(const float* __restrict__ positive, const float* __restrict__ negatives,
        const float* __restrict__ W1, const float* __restrict__ W2,
        const float* __restrict__ b2, const float* __restrict__ W3,
        const float* __restrict__ b3, const float* __restrict__ W4,
        const float* __restrict__ b4) {
    extern __shared__ float sm[];
    float* Ys  = sm;              // 64*256 floats (reused as H2s/H3s later)
    float* H1s = sm + 16384;      // 64*256
    float* Wst = sm + 32768;      // 8192 floats staging
    float* H2s = sm;              // 64*128 (overwrites Ys)
    float* H3s = sm + 8192;       // 64*65 padded (inside old Ys region)

    const int tid = threadIdx.x;
    const int r0  = blockIdx.x * TILE_M;

    // assemble Y tile: row r -> positive (j==0) or negatives[b][j-1]
    for (int i = tid; i < 64 * 64; i += 256) {
        int m = i >> 6, c = i & 63;
        int r = r0 + m;
        int b = r / 17;
        int j = r - b * 17;
        const float* src = (j == 0) ? positive + (size_t)b * 256
                                    : negatives + ((size_t)b * 16 + (j - 1)) * 256;
        ((float4*)Ys)[m * 64 + c] = ((const float4*)src)[c];
    }

    const int m0 = (tid >> 5) * 8;
    const int o0 = (tid & 31) * 8;

    // init accumulators from precomputed anchor partial (contains b1)
    u64 acc[8][4];
    #pragma unroll
    for (int i = 0; i < 8; i++) {
        int r = r0 + m0 + i;
        int b = r / 17;
        const float* a = g_A + (size_t)b * 256 + o0;
        float4 a0 = *(const float4*)a;
        float4 a1 = *(const float4*)(a + 4);
        acc[i][0] = pk(a0.x, a0.y); acc[i][1] = pk(a0.z, a0.w);
        acc[i][2] = pk(a1.x, a1.y); acc[i][3] = pk(a1.z, a1.w);
    }

    // ---- layer 1 (y half): K=256 over W1[:, 256:512]
    for (int kc = 0; kc < 256; kc += 32) {
        __syncthreads();
        load_w<256, 32>(Wst, W1 + 256, 512, kc, tid);
        __syncthreads();
        gemm256_chunk(Ys, Wst, kc, m0, o0, acc);
    }

    // gelu -> H1s
    #pragma unroll
    for (int i = 0; i < 8; i++) {
        float2 p0 = upk(acc[i][0]), p1 = upk(acc[i][1]);
        float2 p2 = upk(acc[i][2]), p3 = upk(acc[i][3]);
        float4 h0 = {gelu_exact(p0.x), gelu_exact(p0.y), gelu_exact(p1.x), gelu_exact(p1.y)};
        float4 h1 = {gelu_exact(p2.x), gelu_exact(p2.y), gelu_exact(p3.x), gelu_exact(p3.y)};
        *(float4*)&H1s[(m0 + i) * 256 + o0]     = h0;
        *(float4*)&H1s[(m0 + i) * 256 + o0 + 4] = h1;
    }

    // ---- layer 2: 64x128, K=256
    const int o2 = (tid & 31) * 4;
    u64 acc2[8][2];
    #pragma unroll
    for (int i = 0; i < 8; i++) { acc2[i][0] = pk(0.f, 0.f); acc2[i][1] = pk(0.f, 0.f); }

    for (int kc = 0; kc < 256; kc += 64) {
        __syncthreads();  // H1s stores visible (1st iter) / Wst reads done
        load_w<128, 64>(Wst, W2, 256, kc, tid);
        __syncthreads();
        #pragma unroll
        for (int k4 = 0; k4 < 64; k4 += 4) {
            float4 xv[8];
            #pragma unroll
            for (int i = 0; i < 8; i++)
                xv[i] = *(const float4*)&H1s[(m0 + i) * 256 + kc + k4];
            const int q  = ((k4 >> 2) & 7) << 2;
            const int oo = o2 ^ q;
            #pragma unroll
            for (int c = 0; c < 4; c++) {
                float4 w = *(const float4*)&Wst[(k4 + c) * 128 + oo];
                u64 wa = pk(w.x, w.y), wb = pk(w.z, w.w);
                #pragma unroll
                for (int i = 0; i < 8; i++) {
                    float x = (c == 0) ? xv[i].x : (c == 1) ? xv[i].y
                            : (c == 2) ? xv[i].z : xv[i].w;
                    u64 xx = pk(x, x);
                    fma2(acc2[i][0], xx, wa);
                    fma2(acc2[i][1], xx, wb);
                }
            }
        }
    }

    __syncthreads();  // everyone done reading Ys(GEMM1)/Wst before H2s store + W3 load
    {
        float4 b2v = *(const float4*)(b2 + o2);
        #pragma unroll
        for (int i = 0; i < 8; i++) {
            float2 p0 = upk(acc2[i][0]), p1 = upk(acc2[i][1]);
            float4 h = {gelu_exact(p0.x + b2v.x), gelu_exact(p0.y + b2v.y),
                        gelu_exact(p1.x + b2v.z), gelu_exact(p1.y + b2v.w)};
            *(float4*)&H2s[(m0 + i) * 128 + o2] = h;
        }
    }
    load_w<64, 128>(Wst, W3, 128, 0, tid);
    __syncthreads();

    // ---- layer 3: 64x64, K=128
    const int o3 = (tid & 31) * 2;
    u64 acc3[8];
    #pragma unroll
    for (int i = 0; i < 8; i++) acc3[i] = pk(0.f, 0.f);

    #pragma unroll
    for (int k4 = 0; k4 < 128; k4 += 4) {
        float4 xv[8];
        #pragma unroll
        for (int i = 0; i < 8; i++)
            xv[i] = *(const float4*)&H2s[(m0 + i) * 128 + k4];
        const int q   = ((k4 >> 2) & 7) << 2;
        const int oo3 = o3 ^ q;
        #pragma unroll
        for (int c = 0; c < 4; c++) {
            float2 w = *(const float2*)&Wst[(k4 + c) * 64 + oo3];
            u64 wv = pk(w.x, w.y);
            #pragma unroll
            for (int i = 0; i < 8; i++) {
                float x = (c == 0) ? xv[i].x : (c == 1) ? xv[i].y
                        : (c == 2) ? xv[i].z : xv[i].w;
                fma2(acc3[i], pk(x, x), wv);
            }
        }
    }

    {
        float2 b3v = *(const float2*)(b3 + o3);
        #pragma unroll
        for (int i = 0; i < 8; i++) {
            float2 p = upk(acc3[i]);
            H3s[(m0 + i) * 65 + o3]     = gelu_exact(p.x + b3v.x);
            H3s[(m0 + i) * 65 + o3 + 1] = gelu_exact(p.y + b3v.y);
        }
    }

    __syncthreads();              // H3s complete, Wst reads done
    if (tid < 64) Wst[tid] = W4[tid];
    __syncthreads();

    // ---- layer 4: dot(64) + b4
    if (tid < 64) {
        float e = b4[0];
        const float* hr = &H3s[tid * 65];
        #pragma unroll
        for (int k = 0; k < 64; k++) e += hr[k] * Wst[k];
        g_energy[r0 + tid] = e;
    }
}

// ---------------------------------------------------------------------------
// Reductions (deterministic trees, no atomics)
// ---------------------------------------------------------------------------
__global__ void reduce1() {
    __shared__ float sl[256], sp[256], sn[256], sa[256];
    const int t = threadIdx.x;
    const int b = blockIdx.x * 256 + t;
    const float* e = &g_energy[(size_t)b * 17];

    float v[17];
    #pragma unroll
    for (int j = 0; j < 17; j++) v[j] = e[j];

    float l0 = -v[0] * TEMP_INV;
    float mx = l0;
    #pragma unroll
    for (int j = 1; j < 17; j++) mx = fmaxf(mx, -v[j] * TEMP_INV);
    float s = 0.f;
    #pragma unroll
    for (int j = 0; j < 17; j++) s += expf(-v[j] * TEMP_INV - mx);
    float loss = mx + logf(s) - l0;

    float pos = v[0];
    float neg = 0.f;
    float ok  = 1.f;
    #pragma unroll
    for (int j = 1; j < 17; j++) {
        neg += v[j];
        if (v[j] < v[0]) ok = 0.f;   // argmin==0 iff no later strictly-smaller
    }

    sl[t] = loss; sp[t] = pos; sn[t] = neg; sa[t] = ok;
    __syncthreads();
    for (int st = 128; st > 0; st >>= 1) {
        if (t < st) {
            sl[t] += sl[t + st]; sp[t] += sp[t + st];
            sn[t] += sn[t + st]; sa[t] += sa[t + st];
        }
        __syncthreads();
    }
    if (t == 0) {
        g_part[blockIdx.x][0] = sl[0];
        g_part[blockIdx.x][1] = sp[0];
        g_part[blockIdx.x][2] = sn[0];
        g_part[blockIdx.x][3] = sa[0];
    }
}

__global__ void reduce2(float* __restrict__ out) {
    __shared__ float s[128][4];
    const int t = threadIdx.x;  // 128
    #pragma unroll
    for (int c = 0; c < 4; c++) s[t][c] = g_part[t][c];
    __syncthreads();
    for (int st = 64; st > 0; st >>= 1) {
        if (t < st) {
            #pragma unroll
            for (int c = 0; c < 4; c++) s[t][c] += s[t + st][c];
        }
        __syncthreads();
    }
    if (t == 0) {
        out[0] = s[0][0] / 32768.0f;               // loss
        out[1] = s[0][1] / 32768.0f;               // pos_energy
        out[2] = s[0][2] / (32768.0f * 16.0f);     // neg_energy
        out[3] = s[0][3] / 32768.0f;               // accuracy
    }
}

// ---------------------------------------------------------------------------
extern "C" void kernel_launch(void* const* d_in, const int* in_sizes, int n_in,
                              void* d_out, int out_size) {
    const float* anchor    = (const float*)d_in[0];
    const float* positive  = (const float*)d_in[1];
    const float* negatives = (const float*)d_in[2];
    const float* W1 = (const float*)d_in[3];
    const float* b1 = (const float*)d_in[4];
    const float* W2 = (const float*)d_in[5];
    const float* b2 = (const float*)d_in[6];
    const float* W3 = (const float*)d_in[7];
    const float* b3 = (const float*)d_in[8];
    const float* W4 = (const float*)d_in[9];
    const float* b4 = (const float*)d_in[10];
    float* out = (float*)d_out;

    const int SMEM_PRE = (64 * 256 + 32 * 256) * 4;                 // 98304
    const int SMEM_EN  = (64 * 256 + 64 * 256 + 8192) * 4;          // 163840
    cudaFuncSetAttribute(precompA, cudaFuncAttributeMaxDynamicSharedMemorySize, SMEM_PRE);
    cudaFuncSetAttribute(energyK,  cudaFuncAttributeMaxDynamicSharedMemorySize, SMEM_EN);

    precompA<<<NB / TILE_M, 256, SMEM_PRE>>>(anchor, W1, b1);
    energyK<<<NBLK, 256, SMEM_EN>>>(positive, negatives, W1, W2, b2, W3, b3, W4, b4);
    reduce1<<<128, 256>>>();
    reduce2<<<1, 128>>>(out);
}

// round 2
// speedup vs baseline: 1.0522x; 1.0522x over previous
#include <cuda_runtime.h>
#include <math.h>

// ---------------------------------------------------------------------------
// ContrastiveEnergyLearning — Round 2: conflict-free weight SMEM layout.
// Outputs per thread are pairs (l + 64j, l + 64j + 32); weights are pre-packed
// into ulonglong2 slots with 16B lane stride so every weight LDS is
// bank-conflict-free. All math exact fp32 (FFMA2 via fma.rn.f32x2).
// ---------------------------------------------------------------------------

#define NB      32768
#define RPB     17
#define RTOT    (NB * RPB)          // 557056
#define TILE_M  64
#define NBLK    (RTOT / TILE_M)     // 8704
#define TEMP_INV (1.0f / 0.07f)

__device__ float g_A[NB * 256];     // anchor @ W1x^T + b1
__device__ float g_energy[RTOT];
__device__ float g_part[128][4];

typedef unsigned long long u64;

__device__ __forceinline__ u64 pk(float x, float y) {
    u64 r; asm("mov.b64 %0,{%1,%2};" : "=l"(r) : "f"(x), "f"(y)); return r;
}
__device__ __forceinline__ float2 upk(u64 v) {
    float2 r; asm("mov.b64 {%0,%1},%2;" : "=f"(r.x), "=f"(r.y) : "l"(v)); return r;
}
__device__ __forceinline__ void fma2(u64 &d, u64 a, u64 b) {
    asm("fma.rn.f32x2 %0,%1,%2,%0;" : "+l"(d) : "l"(a), "l"(b));
}
__device__ __forceinline__ float gelu_exact(float x) {
    return 0.5f * x * (1.0f + erff(x * 0.7071067811865476f));
}

// ---------------------------------------------------------------------------
// Weight staging into pair-packed SMEM.
// Output o = l + 32h (l = lane 0..31, h = 0..NO/32-1), pair j = h>>1,
// half = h&1. Pair j of lane l at (chunk-local) k holds
// (W[l+64j][k], W[l+64j+32][k]).
//   NO>=128: float index = ((((k*(NO/128) + (j>>1))*32 + l)*2 + (j&1))*2 + half
//            -> ulonglong2 slot (k*(NO/128)+jj)*32 + l, 16B lane stride.
//   NO==64 : float index = (k*32 + l)*2 + half -> u64 slot k*32+l, 8B stride.
// Both read patterns are bank-conflict-free.
// ---------------------------------------------------------------------------
template <int NO, int KC>
__device__ __forceinline__ void load_wp(float* Wp, const float* __restrict__ W,
                                        int ld, int k0, int tid) {
    constexpr int NQ = KC / 4;
    #pragma unroll
    for (int i = tid; i < NO * NQ; i += 256) {
        int o  = i / NQ;
        int kg = i - o * NQ;
        float4 v = *(const float4*)(W + (size_t)o * ld + k0 + (kg << 2));
        int l = o & 31, h = o >> 5;
        int j = h >> 1, half = h & 1;
        float vv[4] = {v.x, v.y, v.z, v.w};
        #pragma unroll
        for (int c = 0; c < 4; c++) {
            int k = (kg << 2) + c;
            int fidx;
            if (NO >= 128) {
                int jj = j >> 1, jb = j & 1;
                fidx = ((((k * (NO / 128) + jj) * 32 + l) * 2 + jb) * 2) + half;
            } else {
                fidx = (k * 32 + l) * 2 + half;
            }
            Wp[fidx] = vv[c];
        }
    }
}

// 64-row x 256-out GEMM chunk (K slice KC=64). acc[i][j] = pair (l+64j, l+64j+32).
__device__ __forceinline__ void gemm256(const float* Xs, const float* Wst,
                                        int kc, int m0, int l, u64 acc[8][4]) {
    const ulonglong2* Wv = (const ulonglong2*)Wst;
    #pragma unroll
    for (int k4 = 0; k4 < 64; k4 += 4) {
        float4 xv[8];
        #pragma unroll
        for (int i = 0; i < 8; i++)
            xv[i] = *(const float4*)&Xs[(m0 + i) * 256 + kc + k4];
        #pragma unroll
        for (int c = 0; c < 4; c++) {
            int kk = k4 + c;
            ulonglong2 wA = Wv[(kk * 2 + 0) * 32 + l];
            ulonglong2 wB = Wv[(kk * 2 + 1) * 32 + l];
            #pragma unroll
            for (int i = 0; i < 8; i++) {
                float x = (c == 0) ? xv[i].x : (c == 1) ? xv[i].y
                        : (c == 2) ? xv[i].z : xv[i].w;
                u64 xx = pk(x, x);
                fma2(acc[i][0], xx, wA.x);
                fma2(acc[i][1], xx, wA.y);
                fma2(acc[i][2], xx, wB.x);
                fma2(acc[i][3], xx, wB.y);
            }
        }
    }
}

// ---------------------------------------------------------------------------
// Kernel 1: g_A = anchor @ W1[:, :256]^T + b1
// ---------------------------------------------------------------------------
__global__ void __launch_bounds__(256, 1)
precompA(const float* __restrict__ anchor, const float* __restrict__ W1,
         const float* __restrict__ b1) {
    extern __shared__ float sm[];
    float* Xs  = sm;             // 64*256
    float* Wst = sm + 16384;     // 16384 floats (64 KB)

    const int tid = threadIdx.x;
    const int r0  = blockIdx.x * TILE_M;

    for (int i = tid; i < 64 * 64; i += 256) {
        int m = i >> 6, c = i & 63;
        ((float4*)Xs)[m * 64 + c] =
            ((const float4*)(anchor + (size_t)(r0 + m) * 256))[c];
    }

    const int m0 = (tid >> 5) * 8;
    const int l  = tid & 31;

    u64 bv[4];
    #pragma unroll
    for (int j = 0; j < 4; j++) bv[j] = pk(b1[l + 64 * j], b1[l + 64 * j + 32]);
    u64 acc[8][4];
    #pragma unroll
    for (int i = 0; i < 8; i++)
        #pragma unroll
        for (int j = 0; j < 4; j++) acc[i][j] = bv[j];

    for (int kc = 0; kc < 256; kc += 64) {
        __syncthreads();
        load_wp<256, 64>(Wst, W1, 512, kc, tid);
        __syncthreads();
        gemm256(Xs, Wst, kc, m0, l, acc);
    }

    #pragma unroll
    for (int i = 0; i < 8; i++) {
        size_t base = (size_t)(r0 + m0 + i) * 256 + l;
        #pragma unroll
        for (int j = 0; j < 4; j++) {
            float2 p = upk(acc[i][j]);
            g_A[base + 64 * j]      = p.x;
            g_A[base + 64 * j + 32] = p.y;
        }
    }
}

// ---------------------------------------------------------------------------
// Kernel 2: fused energy
// ---------------------------------------------------------------------------
__global__ void __launch_bounds__(256, 1)
energyK(const float* __restrict__ positive, const float* __restrict__ negatives,
        const float* __restrict__ W1, const float* __restrict__ W2,
        const float* __restrict__ b2, const float* __restrict__ W3,
        const float* __restrict__ b3, const float* __restrict__ W4,
        const float* __restrict__ b4) {
    extern __shared__ float sm[];
    float* Ys  = sm;              // 16384 floats
    float* H1s = sm + 16384;      // 16384
    float* Wst = sm + 32768;      // 16384 (64 KB staging)
    float* H2s = sm;              // 64*128 (reuses Ys)
    float* H3s = sm + 8192;       // 64*65 padded (inside old Ys)

    const int tid = threadIdx.x;
    const int r0  = blockIdx.x * TILE_M;

    // assemble Y tile
    for (int i = tid; i < 64 * 64; i += 256) {
        int m = i >> 6, c = i & 63;
        int r = r0 + m;
        int b = r / 17;
        int j = r - b * 17;
        const float* src = (j == 0) ? positive + (size_t)b * 256
                                    : negatives + ((size_t)b * 16 + (j - 1)) * 256;
        ((float4*)Ys)[m * 64 + c] = ((const float4*)src)[c];
    }

    const int m0 = (tid >> 5) * 8;
    const int l  = tid & 31;

    // init accumulators from precomputed anchor partial (contains b1)
    u64 acc[8][4];
    #pragma unroll
    for (int i = 0; i < 8; i++) {
        int r = r0 + m0 + i;
        int b = r / 17;
        const float* a = g_A + (size_t)b * 256 + l;
        #pragma unroll
        for (int j = 0; j < 4; j++)
            acc[i][j] = pk(a[64 * j], a[64 * j + 32]);
    }

    // ---- layer 1 (y half): K=256 over W1[:, 256:512]
    for (int kc = 0; kc < 256; kc += 64) {
        __syncthreads();
        load_wp<256, 64>(Wst, W1 + 256, 512, kc, tid);
        __syncthreads();
        gemm256(Ys, Wst, kc, m0, l, acc);
    }

    // gelu -> H1s (scalar stores, lane stride 4B: conflict-free)
    #pragma unroll
    for (int i = 0; i < 8; i++) {
        float* hr = &H1s[(m0 + i) * 256 + l];
        #pragma unroll
        for (int j = 0; j < 4; j++) {
            float2 p = upk(acc[i][j]);
            hr[64 * j]      = gelu_exact(p.x);
            hr[64 * j + 32] = gelu_exact(p.y);
        }
    }

    // ---- layer 2: 64x128, K=256. pairs j=0: (l, l+32); j=1: (l+64, l+96)
    u64 acc2[8][2];
    #pragma unroll
    for (int i = 0; i < 8; i++) { acc2[i][0] = 0ULL; acc2[i][1] = 0ULL; }

    for (int kc = 0; kc < 256; kc += 64) {
        __syncthreads();
        load_wp<128, 64>(Wst, W2, 256, kc, tid);
        __syncthreads();
        const ulonglong2* Wv = (const ulonglong2*)Wst;
        #pragma unroll
        for (int k4 = 0; k4 < 64; k4 += 4) {
            float4 xv[8];
            #pragma unroll
            for (int i = 0; i < 8; i++)
                xv[i] = *(const float4*)&H1s[(m0 + i) * 256 + kc + k4];
            #pragma unroll
            for (int c = 0; c < 4; c++) {
                ulonglong2 wA = Wv[(k4 + c) * 32 + l];
                #pragma unroll
                for (int i = 0; i < 8; i++) {
                    float x = (c == 0) ? xv[i].x : (c == 1) ? xv[i].y
                            : (c == 2) ? xv[i].z : xv[i].w;
                    u64 xx = pk(x, x);
                    fma2(acc2[i][0], xx, wA.x);
                    fma2(acc2[i][1], xx, wA.y);
                }
            }
        }
    }

    __syncthreads();  // all Wst/Ys reads done before H2s store + W3 staging
    {
        float b2a = b2[l], b2b = b2[l + 32], b2c = b2[l + 64], b2d = b2[l + 96];
        #pragma unroll
        for (int i = 0; i < 8; i++) {
            float2 p0 = upk(acc2[i][0]), p1 = upk(acc2[i][1]);
            float* hr = &H2s[(m0 + i) * 128 + l];
            hr[0]  = gelu_exact(p0.x + b2a);
            hr[32] = gelu_exact(p0.y + b2b);
            hr[64] = gelu_exact(p1.x + b2c);
            hr[96] = gelu_exact(p1.y + b2d);
        }
    }
    load_wp<64, 128>(Wst, W3, 128, 0, tid);
    __syncthreads();

    // ---- layer 3: 64x64, K=128. pair (l, l+32)
    u64 acc3[8];
    #pragma unroll
    for (int i = 0; i < 8; i++) acc3[i] = 0ULL;

    const u64* Wv3 = (const u64*)Wst;
    #pragma unroll
    for (int k4 = 0; k4 < 128; k4 += 4) {
        float4 xv[8];
        #pragma unroll
        for (int i = 0; i < 8; i++)
            xv[i] = *(const float4*)&H2s[(m0 + i) * 128 + k4];
        #pragma unroll
        for (int c = 0; c < 4; c++) {
            u64 wv = Wv3[(k4 + c) * 32 + l];
            #pragma unroll
            for (int i = 0; i < 8; i++) {
                float x = (c == 0) ? xv[i].x : (c == 1) ? xv[i].y
                        : (c == 2) ? xv[i].z : xv[i].w;
                fma2(acc3[i], pk(x, x), wv);
            }
        }
    }

    {
        float b3a = b3[l], b3b = b3[l + 32];
        #pragma unroll
        for (int i = 0; i < 8; i++) {
            float2 p = upk(acc3[i]);
            H3s[(m0 + i) * 65 + l]      = gelu_exact(p.x + b3a);
            H3s[(m0 + i) * 65 + l + 32] = gelu_exact(p.y + b3b);
        }
    }

    __syncthreads();              // H3s complete, layer-3 Wst reads done
    if (tid < 64) Wst[tid] = W4[tid];
    __syncthreads();

    // ---- layer 4: dot(64) + b4
    if (tid < 64) {
        float e = b4[0];
        const float* hr = &H3s[tid * 65];
        #pragma unroll
        for (int k = 0; k < 64; k++) e += hr[k] * Wst[k];
        g_energy[r0 + tid] = e;
    }
}

// ---------------------------------------------------------------------------
// Reductions (deterministic trees, no atomics)
// ---------------------------------------------------------------------------
__global__ void reduce1() {
    __shared__ float sl[256], sp[256], sn[256], sa[256];
    const int t = threadIdx.x;
    const int b = blockIdx.x * 256 + t;
    const float* e = &g_energy[(size_t)b * 17];

    float v[17];
    #pragma unroll
    for (int j = 0; j < 17; j++) v[j] = e[j];

    float l0 = -v[0] * TEMP_INV;
    float mx = l0;
    #pragma unroll
    for (int j = 1; j < 17; j++) mx = fmaxf(mx, -v[j] * TEMP_INV);
    float s = 0.f;
    #pragma unroll
    for (int j = 0; j < 17; j++) s += expf(-v[j] * TEMP_INV - mx);
    float loss = mx + logf(s) - l0;

    float pos = v[0];
    float neg = 0.f;
    float ok  = 1.f;
    #pragma unroll
    for (int j = 1; j < 17; j++) {
        neg += v[j];
        if (v[j] < v[0]) ok = 0.f;
    }

    sl[t] = loss; sp[t] = pos; sn[t] = neg; sa[t] = ok;
    __syncthreads();
    for (int st = 128; st > 0; st >>= 1) {
        if (t < st) {
            sl[t] += sl[t + st]; sp[t] += sp[t + st];
            sn[t] += sn[t + st]; sa[t] += sa[t + st];
        }
        __syncthreads();
    }
    if (t == 0) {
        g_part[blockIdx.x][0] = sl[0];
        g_part[blockIdx.x][1] = sp[0];
        g_part[blockIdx.x][2] = sn[0];
        g_part[blockIdx.x][3] = sa[0];
    }
}

__global__ void reduce2(float* __restrict__ out) {
    __shared__ float s[128][4];
    const int t = threadIdx.x;
    #pragma unroll
    for (int c = 0; c < 4; c++) s[t][c] = g_part[t][c];
    __syncthreads();
    for (int st = 64; st > 0; st >>= 1) {
        if (t < st) {
            #pragma unroll
            for (int c = 0; c < 4; c++) s[t][c] += s[t + st][c];
        }
        __syncthreads();
    }
    if (t == 0) {
        out[0] = s[0][0] / 32768.0f;
        out[1] = s[0][1] / 32768.0f;
        out[2] = s[0][2] / (32768.0f * 16.0f);
        out[3] = s[0][3] / 32768.0f;
    }
}

// ---------------------------------------------------------------------------
extern "C" void kernel_launch(void* const* d_in, const int* in_sizes, int n_in,
                              void* d_out, int out_size) {
    const float* anchor    = (const float*)d_in[0];
    const float* positive  = (const float*)d_in[1];
    const float* negatives = (const float*)d_in[2];
    const float* W1 = (const float*)d_in[3];
    const float* b1 = (const float*)d_in[4];
    const float* W2 = (const float*)d_in[5];
    const float* b2 = (const float*)d_in[6];
    const float* W3 = (const float*)d_in[7];
    const float* b3 = (const float*)d_in[8];
    const float* W4 = (const float*)d_in[9];
    const float* b4 = (const float*)d_in[10];
    float* out = (float*)d_out;

    const int SMEM_PRE = (16384 + 16384) * 4;          // 128 KB
    const int SMEM_EN  = (16384 * 3) * 4;              // 192 KB
    cudaFuncSetAttribute(precompA, cudaFuncAttributeMaxDynamicSharedMemorySize, SMEM_PRE);
    cudaFuncSetAttribute(energyK,  cudaFuncAttributeMaxDynamicSharedMemorySize, SMEM_EN);

    precompA<<<NB / TILE_M, 256, SMEM_PRE>>>(anchor, W1, b1);
    energyK<<<NBLK, 256, SMEM_EN>>>(positive, negatives, W1, W2, b2, W3, b3, W4, b4);
    reduce1<<<128, 256>>>();
    reduce2<<<1, 128>>>(out);
}

// round 3
// speedup vs baseline: 1.0584x; 1.0059x over previous
#include <cuda_runtime.h>
#include <math.h>

// ---------------------------------------------------------------------------
// ContrastiveEnergyLearning — Round 2: conflict-free weight SMEM layout.
// Outputs per thread are pairs (l + 64j, l + 64j + 32); weights are pre-packed
// into ulonglong2 slots with 16B lane stride so every weight LDS is
// bank-conflict-free. All math exact fp32 (FFMA2 via fma.rn.f32x2).
// ---------------------------------------------------------------------------

#define NB      32768
#define RPB     17
#define RTOT    (NB * RPB)          // 557056
#define TILE_M  64
#define NBLK    (RTOT / TILE_M)     // 8704
#define TEMP_INV (1.0f / 0.07f)

__device__ float g_A[NB * 256];     // anchor @ W1x^T + b1
__device__ float g_energy[RTOT];
__device__ float g_part[128][4];

typedef unsigned long long u64;

__device__ __forceinline__ u64 pk(float x, float y) {
    u64 r; asm("mov.b64 %0,{%1,%2};" : "=l"(r) : "f"(x), "f"(y)); return r;
}
__device__ __forceinline__ float2 upk(u64 v) {
    float2 r; asm("mov.b64 {%0,%1},%2;" : "=f"(r.x), "=f"(r.y) : "l"(v)); return r;
}
__device__ __forceinline__ void fma2(u64 &d, u64 a, u64 b) {
    asm("fma.rn.f32x2 %0,%1,%2,%0;" : "+l"(d) : "l"(a), "l"(b));
}
__device__ __forceinline__ float gelu_exact(float x) {
    return 0.5f * x * (1.0f + erff(x * 0.7071067811865476f));
}

// ---------------------------------------------------------------------------
// Weight staging into pair-packed SMEM.
// Output o = l + 32h (l = lane 0..31, h = 0..NO/32-1), pair j = h>>1,
// half = h&1. Pair j of lane l at (chunk-local) k holds
// (W[l+64j][k], W[l+64j+32][k]).
//   NO>=128: float index = ((((k*(NO/128) + (j>>1))*32 + l)*2 + (j&1))*2 + half
//            -> ulonglong2 slot (k*(NO/128)+jj)*32 + l, 16B lane stride.
//   NO==64 : float index = (k*32 + l)*2 + half -> u64 slot k*32+l, 8B stride.
// Both read patterns are bank-conflict-free.
// ---------------------------------------------------------------------------
template <int NO, int KC>
__device__ __forceinline__ void load_wp(float* Wp, const float* __restrict__ W,
                                        int ld, int k0, int tid) {
    constexpr int NQ = KC / 4;
    #pragma unroll
    for (int i = tid; i < NO * NQ; i += 256) {
        int o  = i / NQ;
        int kg = i - o * NQ;
        float4 v = *(const float4*)(W + (size_t)o * ld + k0 + (kg << 2));
        int l = o & 31, h = o >> 5;
        int j = h >> 1, half = h & 1;
        float vv[4] = {v.x, v.y, v.z, v.w};
        #pragma unroll
        for (int c = 0; c < 4; c++) {
            int k = (kg << 2) + c;
            int fidx;
            if (NO >= 128) {
                int jj = j >> 1, jb = j & 1;
                fidx = ((((k * (NO / 128) + jj) * 32 + l) * 2 + jb) * 2) + half;
            } else {
                fidx = (k * 32 + l) * 2 + half;
            }
            Wp[fidx] = vv[c];
        }
    }
}

// 64-row x 256-out GEMM chunk (K slice KC=64). acc[i][j] = pair (l+64j, l+64j+32).
__device__ __forceinline__ void gemm256(const float* Xs, const float* Wst,
                                        int kc, int m0, int l, u64 acc[8][4]) {
    const ulonglong2* Wv = (const ulonglong2*)Wst;
    #pragma unroll
    for (int k4 = 0; k4 < 64; k4 += 4) {
        float4 xv[8];
        #pragma unroll
        for (int i = 0; i < 8; i++)
            xv[i] = *(const float4*)&Xs[(m0 + i) * 256 + kc + k4];
        #pragma unroll
        for (int c = 0; c < 4; c++) {
            int kk = k4 + c;
            ulonglong2 wA = Wv[(kk * 2 + 0) * 32 + l];
            ulonglong2 wB = Wv[(kk * 2 + 1) * 32 + l];
            #pragma unroll
            for (int i = 0; i < 8; i++) {
                float x = (c == 0) ? xv[i].x : (c == 1) ? xv[i].y
                        : (c == 2) ? xv[i].z : xv[i].w;
                u64 xx = pk(x, x);
                fma2(acc[i][0], xx, wA.x);
                fma2(acc[i][1], xx, wA.y);
                fma2(acc[i][2], xx, wB.x);
                fma2(acc[i][3], xx, wB.y);
            }
        }
    }
}

// ---------------------------------------------------------------------------
// Kernel 1: g_A = anchor @ W1[:, :256]^T + b1
// ---------------------------------------------------------------------------
__global__ void __launch_bounds__(256, 1)
precompA(const float* __restrict__ anchor, const float* __restrict__ W1,
         const float* __restrict__ b1) {
    extern __shared__ float sm[];
    float* Xs  = sm;             // 64*256
    float* Wst = sm + 16384;     // 16384 floats (64 KB)

    const int tid = threadIdx.x;
    const int r0  = blockIdx.x * TILE_M;

    for (int i = tid; i < 64 * 64; i += 256) {
        int m = i >> 6, c = i & 63;
        ((float4*)Xs)[m * 64 + c] =
            ((const float4*)(anchor + (size_t)(r0 + m) * 256))[c];
    }

    const int m0 = (tid >> 5) * 8;
    const int l  = tid & 31;

    u64 bv[4];
    #pragma unroll
    for (int j = 0; j < 4; j++) bv[j] = pk(b1[l + 64 * j], b1[l + 64 * j + 32]);
    u64 acc[8][4];
    #pragma unroll
    for (int i = 0; i < 8; i++)
        #pragma unroll
        for (int j = 0; j < 4; j++) acc[i][j] = bv[j];

    for (int kc = 0; kc < 256; kc += 64) {
        __syncthreads();
        load_wp<256, 64>(Wst, W1, 512, kc, tid);
        __syncthreads();
        gemm256(Xs, Wst, kc, m0, l, acc);
    }

    #pragma unroll
    for (int i = 0; i < 8; i++) {
        size_t base = (size_t)(r0 + m0 + i) * 256 + l;
        #pragma unroll
        for (int j = 0; j < 4; j++) {
            float2 p = upk(acc[i][j]);
            g_A[base + 64 * j]      = p.x;
            g_A[base + 64 * j + 32] = p.y;
        }
    }
}

// ---------------------------------------------------------------------------
// Kernel 2: fused energy
// ---------------------------------------------------------------------------
__global__ void __launch_bounds__(256, 1)
energyK(const float* __restrict__ positive, const float* __restrict__ negatives,
        const float* __restrict__ W1, const float* __restrict__ W2,
        const float* __restrict__ b2, const float* __restrict__ W3,
        const float* __restrict__ b3, const float* __restrict__ W4,
        const float* __restrict__ b4) {
    extern __shared__ float sm[];
    float* Ys  = sm;              // 16384 floats
    float* H1s = sm + 16384;      // 16384
    float* Wst = sm + 32768;      // 16384 (64 KB staging)
    float* H2s = sm;              // 64*128 (reuses Ys)
    float* H3s = sm + 8192;       // 64*65 padded (inside old Ys)

    const int tid = threadIdx.x;
    const int r0  = blockIdx.x * TILE_M;

    // assemble Y tile
    for (int i = tid; i < 64 * 64; i += 256) {
        int m = i >> 6, c = i & 63;
        int r = r0 + m;
        int b = r / 17;
        int j = r - b * 17;
        const float* src = (j == 0) ? positive + (size_t)b * 256
                                    : negatives + ((size_t)b * 16 + (j - 1)) * 256;
        ((float4*)Ys)[m * 64 + c] = ((const float4*)src)[c];
    }

    const int m0 = (tid >> 5) * 8;
    const int l  = tid & 31;

    // init accumulators from precomputed anchor partial (contains b1)
    u64 acc[8][4];
    #pragma unroll
    for (int i = 0; i < 8; i++) {
        int r = r0 + m0 + i;
        int b = r / 17;
        const float* a = g_A + (size_t)b * 256 + l;
        #pragma unroll
        for (int j = 0; j < 4; j++)
            acc[i][j] = pk(a[64 * j], a[64 * j + 32]);
    }

    // ---- layer 1 (y half): K=256 over W1[:, 256:512]
    for (int kc = 0; kc < 256; kc += 64) {
        __syncthreads();
        load_wp<256, 64>(Wst, W1 + 256, 512, kc, tid);
        __syncthreads();
        gemm256(Ys, Wst, kc, m0, l, acc);
    }

    // gelu -> H1s (scalar stores, lane stride 4B: conflict-free)
    #pragma unroll
    for (int i = 0; i < 8; i++) {
        float* hr = &H1s[(m0 + i) * 256 + l];
        #pragma unroll
        for (int j = 0; j < 4; j++) {
            float2 p = upk(acc[i][j]);
            hr[64 * j]      = gelu_exact(p.x);
            hr[64 * j + 32] = gelu_exact(p.y);
        }
    }

    // ---- layer 2: 64x128, K=256. pairs j=0: (l, l+32); j=1: (l+64, l+96)
    u64 acc2[8][2];
    #pragma unroll
    for (int i = 0; i < 8; i++) { acc2[i][0] = 0ULL; acc2[i][1] = 0ULL; }

    for (int kc = 0; kc < 256; kc += 64) {
        __syncthreads();
        load_wp<128, 64>(Wst, W2, 256, kc, tid);
        __syncthreads();
        const ulonglong2* Wv = (const ulonglong2*)Wst;
        #pragma unroll
        for (int k4 = 0; k4 < 64; k4 += 4) {
            float4 xv[8];
            #pragma unroll
            for (int i = 0; i < 8; i++)
                xv[i] = *(const float4*)&H1s[(m0 + i) * 256 + kc + k4];
            #pragma unroll
            for (int c = 0; c < 4; c++) {
                ulonglong2 wA = Wv[(k4 + c) * 32 + l];
                #pragma unroll
                for (int i = 0; i < 8; i++) {
                    float x = (c == 0) ? xv[i].x : (c == 1) ? xv[i].y
                            : (c == 2) ? xv[i].z : xv[i].w;
                    u64 xx = pk(x, x);
                    fma2(acc2[i][0], xx, wA.x);
                    fma2(acc2[i][1], xx, wA.y);
                }
            }
        }
    }

    __syncthreads();  // all Wst/Ys reads done before H2s store + W3 staging
    {
        float b2a = b2[l], b2b = b2[l + 32], b2c = b2[l + 64], b2d = b2[l + 96];
        #pragma unroll
        for (int i = 0; i < 8; i++) {
            float2 p0 = upk(acc2[i][0]), p1 = upk(acc2[i][1]);
            float* hr = &H2s[(m0 + i) * 128 + l];
            hr[0]  = gelu_exact(p0.x + b2a);
            hr[32] = gelu_exact(p0.y + b2b);
            hr[64] = gelu_exact(p1.x + b2c);
            hr[96] = gelu_exact(p1.y + b2d);
        }
    }
    load_wp<64, 128>(Wst, W3, 128, 0, tid);
    __syncthreads();

    // ---- layer 3: 64x64, K=128. pair (l, l+32)
    u64 acc3[8];
    #pragma unroll
    for (int i = 0; i < 8; i++) acc3[i] = 0ULL;

    const u64* Wv3 = (const u64*)Wst;
    #pragma unroll
    for (int k4 = 0; k4 < 128; k4 += 4) {
        float4 xv[8];
        #pragma unroll
        for (int i = 0; i < 8; i++)
            xv[i] = *(const float4*)&H2s[(m0 + i) * 128 + k4];
        #pragma unroll
        for (int c = 0; c < 4; c++) {
            u64 wv = Wv3[(k4 + c) * 32 + l];
            #pragma unroll
            for (int i = 0; i < 8; i++) {
                float x = (c == 0) ? xv[i].x : (c == 1) ? xv[i].y
                        : (c == 2) ? xv[i].z : xv[i].w;
                fma2(acc3[i], pk(x, x), wv);
            }
        }
    }

    {
        float b3a = b3[l], b3b = b3[l + 32];
        #pragma unroll
        for (int i = 0; i < 8; i++) {
            float2 p = upk(acc3[i]);
            H3s[(m0 + i) * 65 + l]      = gelu_exact(p.x + b3a);
            H3s[(m0 + i) * 65 + l + 32] = gelu_exact(p.y + b3b);
        }
    }

    __syncthreads();              // H3s complete, layer-3 Wst reads done
    if (tid < 64) Wst[tid] = W4[tid];
    __syncthreads();

    // ---- layer 4: dot(64) + b4
    if (tid < 64) {
        float e = b4[0];
        const float* hr = &H3s[tid * 65];
        #pragma unroll
        for (int k = 0; k < 64; k++) e += hr[k] * Wst[k];
        g_energy[r0 + tid] = e;
    }
}

// ---------------------------------------------------------------------------
// Reductions (deterministic trees, no atomics)
// ---------------------------------------------------------------------------
__global__ void reduce1() {
    __shared__ float sl[256], sp[256], sn[256], sa[256];
    const int t = threadIdx.x;
    const int b = blockIdx.x * 256 + t;
    const float* e = &g_energy[(size_t)b * 17];

    float v[17];
    #pragma unroll
    for (int j = 0; j < 17; j++) v[j] = e[j];

    float l0 = -v[0] * TEMP_INV;
    float mx = l0;
    #pragma unroll
    for (int j = 1; j < 17; j++) mx = fmaxf(mx, -v[j] * TEMP_INV);
    float s = 0.f;
    #pragma unroll
    for (int j = 0; j < 17; j++) s += expf(-v[j] * TEMP_INV - mx);
    float loss = mx + logf(s) - l0;

    float pos = v[0];
    float neg = 0.f;
    float ok  = 1.f;
    #pragma unroll
    for (int j = 1; j < 17; j++) {
        neg += v[j];
        if (v[j] < v[0]) ok = 0.f;
    }

    sl[t] = loss; sp[t] = pos; sn[t] = neg; sa[t] = ok;
    __syncthreads();
    for (int st = 128; st > 0; st >>= 1) {
        if (t < st) {
            sl[t] += sl[t + st]; sp[t] += sp[t + st];
            sn[t] += sn[t + st]; sa[t] += sa[t + st];
        }
        __syncthreads();
    }
    if (t == 0) {
        g_part[blockIdx.x][0] = sl[0];
        g_part[blockIdx.x][1] = sp[0];
        g_part[blockIdx.x][2] = sn[0];
        g_part[blockIdx.x][3] = sa[0];
    }
}

__global__ void reduce2(float* __restrict__ out) {
    __shared__ float s[128][4];
    const int t = threadIdx.x;
    #pragma unroll
    for (int c = 0; c < 4; c++) s[t][c] = g_part[t][c];
    __syncthreads();
    for (int st = 64; st > 0; st >>= 1) {
        if (t < st) {
            #pragma unroll
            for (int c = 0; c < 4; c++) s[t][c] += s[t + st][c];
        }
        __syncthreads();
    }
    if (t == 0) {
        out[0] = s[0][0] / 32768.0f;
        out[1] = s[0][1] / 32768.0f;
        out[2] = s[0][2] / (32768.0f * 16.0f);
        out[3] = s[0][3] / 32768.0f;
    }
}

// ---------------------------------------------------------------------------
extern "C" void kernel_launch(void* const* d_in, const int* in_sizes, int n_in,
                              void* d_out, int out_size) {
    const float* anchor    = (const float*)d_in[0];
    const float* positive  = (const float*)d_in[1];
    const float* negatives = (const float*)d_in[2];
    const float* W1 = (const float*)d_in[3];
    const float* b1 = (const float*)d_in[4];
    const float* W2 = (const float*)d_in[5];
    const float* b2 = (const float*)d_in[6];
    const float* W3 = (const float*)d_in[7];
    const float* b3 = (const float*)d_in[8];
    const float* W4 = (const float*)d_in[9];
    const float* b4 = (const float*)d_in[10];
    float* out = (float*)d_out;

    const int SMEM_PRE = (16384 + 16384) * 4;          // 128 KB
    const int SMEM_EN  = (16384 * 3) * 4;              // 192 KB
    cudaFuncSetAttribute(precompA, cudaFuncAttributeMaxDynamicSharedMemorySize, SMEM_PRE);
    cudaFuncSetAttribute(energyK,  cudaFuncAttributeMaxDynamicSharedMemorySize, SMEM_EN);

    precompA<<<NB / TILE_M, 256, SMEM_PRE>>>(anchor, W1, b1);
    energyK<<<NBLK, 256, SMEM_EN>>>(positive, negatives, W1, W2, b2, W3, b3, W4, b4);
    reduce1<<<128, 256>>>();
    reduce2<<<1, 128>>>(out);
}